// round 6
// baseline (speedup 1.0000x reference)
#include <cuda_runtime.h>
#include <math.h>

// ROI pooling, single ROI, POOL = 7x7, SCALE_FACTOR = 1.0
// img: (1, 512, 512, 256) fp32 NHWC   -> d_in[0]
// roi: (1, 5) fp32 [_, x_min, y_min, x_max, y_max] -> d_in[1]
// out: (1, 256, 7, 7) fp32            -> d_out
//
// out[c*49 + py*7 + px] = img[((iy*512) + ix)*256 + c]
// iy = clip(y_min + floor(py * (h/7)), y_min, y_max), same for ix.
//
// Index math mirrors the JAX reference bit-exactly in fp32:
//   jnp.round -> rintf (round-half-to-even), h/7 in fp32, floorf.
//
// Latency-bound micro-kernel: 49 blocks x 64 threads (2 warps/block),
// each thread loads one float4 of channels (coalesced LDG.128), writes
// 4 scalar stores (stride-49 scatter, absorbed by L2; total out = 50KB).
// roi read as one aligned float4 + one scalar (2 independent loads
// instead of 4), then the single dependent img load.

#define IMG_COLS 512
#define IMG_C    256
#define PH 7
#define PW 7

__global__ __launch_bounds__(64)
void roi_pool_kernel(const float4* __restrict__ img4,
                     const float*  __restrict__ roi,
                     float* __restrict__ out)
{
    const int p  = blockIdx.x;        // pooled pixel 0..48
    const int py = p / PW;
    const int px = p % PW;
    const int t  = threadIdx.x;       // channel group 0..63 (4 ch each)

    // roi[0..3] is 16B-aligned (buffer base alignment) -> one LDG.128.
    const float4 r03 = *(const float4*)roi;   // {_, x_min, y_min, x_max}
    const float  r4  = roi[4];                //  y_max

    const int x_min = (int)rintf(r03.y);
    const int y_min = (int)rintf(r03.z);
    const int x_max = (int)rintf(r03.w);
    const int y_max = (int)rintf(r4);

    const float h = (float)(y_max - y_min + 1);
    const float w = (float)(x_max - x_min + 1);

    int iy = y_min + (int)floorf((float)py * (h / 7.0f));
    int ix = x_min + (int)floorf((float)px * (w / 7.0f));
    iy = min(max(iy, y_min), y_max);
    ix = min(max(ix, x_min), x_max);

    // One coalesced 16B load per thread: 64 threads x 16B = the pixel's
    // full 1KB channel vector.
    const float4 v = img4[((iy * IMG_COLS) + ix) * (IMG_C / 4) + t];

    // NCHW output: out[c*49 + p]; c = 4*t .. 4*t+3.
    const int base = (4 * t) * (PH * PW) + p;
    out[base]              = v.x;
    out[base + PH * PW]    = v.y;
    out[base + 2 * PH * PW] = v.z;
    out[base + 3 * PH * PW] = v.w;
}

extern "C" void kernel_launch(void* const* d_in, const int* in_sizes, int n_in,
                              void* d_out, int out_size)
{
    const float4* img4 = (const float4*)d_in[0];
    const float*  roi  = (const float*)d_in[1];
    float* out = (float*)d_out;

    roi_pool_kernel<<<PH * PW, 64>>>(img4, roi, out);
}